// round 6
// baseline (speedup 1.0000x reference)
#include <cuda_runtime.h>
#include <math.h>

#define BB 64
#define PP 16320
#define CC 81
#define OO 50
#define CHUNK 2048   // priors per block in k_match (8 per thread)

// ---------------- scratch ----------------
__device__ unsigned char      d_posf[BB * PP];      // positive flag (bytes)
__device__ int                d_bti [BB * PP];      // best_truth_idx
__device__ unsigned long long d_bp64[BB * OO];      // per-truth best (ratio_bits<<32 | ~p)
__device__ float              d_ce  [BB * PP];      // shared neg CE
__device__ int                d_plist[BB * PP];     // compacted positive rows
__device__ int                d_pcount;
__device__ int                d_npos[BB];
__device__ float              d_accB[BB * 4];       // [b][0]=loc,[1]=conf,[2]=obj

// ---------------- init (must precede k_match: all blocks write d_bp64) ----------------
__global__ void k_init() {
    int t = blockIdx.x * blockDim.x + threadIdx.x;
    if (t < BB * OO) d_bp64[t] = 0xFFFFFFFFull;     // ratio=0, p=0 (reference all-zero case)
    if (t < BB * 4) d_accB[t] = 0.f;
    if (t < BB) d_npos[t] = 0;
    if (t == 0) d_pcount = 0;
}

// ---------------- fused match: one pass over the O x P IoU matrix ----------------
__global__ void __launch_bounds__(256) k_match(const float* __restrict__ priors,
                                               const float* __restrict__ targets) {
    int b = blockIdx.y;
    int tid = threadIdx.x;
    __shared__ float4 s_c[OO];
    __shared__ float  s_a[OO];
    __shared__ unsigned long long s_key[OO];
    if (tid < OO) {
        const float* t = targets + (b * OO + tid) * 5;
        float4 c = make_float4(t[0], t[1], t[2], t[3]);
        s_c[tid] = c;
        s_a[tid] = (c.z - c.x) * (c.w - c.y);
        s_key[tid] = 0xFFFFFFFFull;
    }
    __syncthreads();

    int base = blockIdx.x * CHUNK + tid;
    // register-resident prior data, 8 priors per thread
    float px1[8], py1[8], px2[8], py2[8], pa[8];
    float bn[8], bd[8]; int bi[8];
    #pragma unroll
    for (int j = 0; j < 8; j++) {
        int p = base + j * 256;
        float4 pr = (p < PP) ? ((const float4*)priors)[p]
                             : make_float4(-10.f, -10.f, 0.f, 0.f);  // degenerate: inter=0
        px1[j] = pr.x - pr.z * 0.5f; py1[j] = pr.y - pr.w * 0.5f;
        px2[j] = pr.x + pr.z * 0.5f; py2[j] = pr.y + pr.w * 0.5f;
        pa[j] = (px2[j] - px1[j]) * (py2[j] - py1[j]);
        bn[j] = 0.f; bd[j] = 1.f; bi[j] = 0;
    }

    volatile unsigned* keyhi = ((volatile unsigned*)s_key) + 1;  // hi word of each u64
    for (int o = 0; o < OO; o++) {
        float4 c = s_c[o];
        float sa = s_a[o];
        float cached = __uint_as_float(keyhi[2 * o]);   // monotone; stale-low is safe
        #pragma unroll
        for (int j = 0; j < 8; j++) {
            float iw = fmaxf(fminf(c.z, px2[j]) - fmaxf(c.x, px1[j]), 0.f);
            float ih = fmaxf(fminf(c.w, py2[j]) - fmaxf(c.y, py1[j]), 0.f);
            float inter = iw * ih;
            float den = (pa[j] + sa) - inter;
            // per-prior argmax (exact cross-multiplied compare, first-max semantics)
            bool better = inter * bd[j] > bn[j] * den;
            bn[j] = better ? inter : bn[j];
            bd[j] = better ? den   : bd[j];
            bi[j] = better ? o     : bi[j];
            // per-truth argmax: cheap guard, exact rare path
            float r = inter * __frcp_rn(den);
            if (inter > 0.f && r * 1.00002f >= cached) {
                float re = inter / den;   // reference-rounded ratio
                unsigned long long key = ((unsigned long long)__float_as_uint(re) << 32)
                                       | (unsigned)(0xFFFFFFFFu - (unsigned)(base + j * 256));
                atomicMax(&s_key[o], key);
                cached = __uint_as_float(keyhi[2 * o]);
            }
        }
    }
    #pragma unroll
    for (int j = 0; j < 8; j++) {
        int p = base + j * 256;
        if (p < PP) {
            d_posf[b * PP + p] = (bn[j] + bn[j] >= bd[j]) ? 1 : 0;   // IoU >= 0.5
            d_bti[b * PP + p] = bi[j];
        }
    }
    __syncthreads();
    if (tid < OO) atomicMax(&d_bp64[b * OO + tid], s_key[tid]);
}

// ---------------- force best-prior matches (parallel last-writer-wins) ----------------
__global__ void k_force() {
    int b = blockIdx.x;
    int o = threadIdx.x;
    __shared__ int sp[OO];
    if (o < OO) sp[o] = (int)(0xFFFFFFFFu - (unsigned)(d_bp64[b * OO + o] & 0xFFFFFFFFu));
    __syncthreads();
    if (o >= OO) return;
    int p = sp[o];
    for (int o2 = o + 1; o2 < OO; o2++)      // later truth wins on duplicate priors
        if (sp[o2] == p) return;
    d_posf[b * PP + p] = 1;
    d_bti[b * PP + p] = o;
}

// ---------------- negative pass: 4 rows/thread, warp-aggregated compaction ----------
__global__ void __launch_bounds__(256) k_neg(const float* __restrict__ obj) {
    int i4 = blockIdx.x * 256 + threadIdx.x;        // handles rows 4*i4 .. 4*i4+3
    int lane = threadIdx.x & 31;
    const float4* o4 = (const float4*)obj;
    float4 oa = o4[2 * i4];                         // rows 0,1 (o0,o1,o0,o1)
    float4 ob = o4[2 * i4 + 1];                     // rows 2,3
    uchar4 f = ((const uchar4*)d_posf)[i4];

    float dd[4] = {oa.y - oa.x, oa.w - oa.z, ob.y - ob.x, ob.w - ob.z};
    bool  ps[4] = {f.x != 0, f.y != 0, f.z != 0, f.w != 0};
    float ce[4];
    int cnt = 0;
    float spn = 0.f;
    #pragma unroll
    for (int j = 0; j < 4; j++) {
        float lt = __logf(1.f + __expf(-fabsf(dd[j])));
        ce[j] = ps[j] ? 0.f : (fmaxf(dd[j], 0.f) + lt);     // lse(obj)-o0
        if (ps[j]) { cnt++; spn += fmaxf(-dd[j], 0.f) + lt; } // lse(obj)-o1
    }
    ((float4*)d_ce)[i4] = make_float4(ce[0], ce[1], ce[2], ce[3]);

    unsigned any = __ballot_sync(0xFFFFFFFFu, cnt != 0);
    if (any == 0) return;
    int b = (4 * i4) / PP;                          // PP%4==0: b uniform per thread
    // warp exclusive scan of cnt for compaction slots
    int scan = cnt;
    #pragma unroll
    for (int s = 1; s < 32; s <<= 1) {
        int v = __shfl_up_sync(0xFFFFFFFFu, scan, s);
        if (lane >= s) scan += v;
    }
    int total = __shfl_sync(0xFFFFFFFFu, scan, 31);
    int excl = scan - cnt;
    int baseslot = 0;
    if (lane == 31) baseslot = atomicAdd(&d_pcount, total);
    baseslot = __shfl_sync(0xFFFFFFFFu, baseslot, 31);
    if (cnt) {
        atomicAdd(&d_npos[b], cnt);
        atomicAdd(&d_accB[b * 4 + 2], spn);
        int slot = baseslot + excl;
        #pragma unroll
        for (int j = 0; j < 4; j++)
            if (ps[j]) d_plist[slot++] = 4 * i4 + j;
    }
}

// ---------------- positive pass: warp per positive row ----------------
__global__ void __launch_bounds__(256) k_pos(const float* __restrict__ loc,
                                             const float* __restrict__ conf,
                                             const float* __restrict__ obj,
                                             const float* __restrict__ priors,
                                             const float* __restrict__ targets) {
    int nwarps = (gridDim.x * blockDim.x) >> 5;
    int w = (blockIdx.x * blockDim.x + threadIdx.x) >> 5;
    int lane = threadIdx.x & 31;
    int n = d_pcount;
    for (; w < n; w += nwarps) {
        int gw = d_plist[w];
        const float* crow = conf + (size_t)gw * CC;
        float a0 = crow[lane];
        float a1 = crow[lane + 32];
        float a2 = (lane < 17) ? crow[lane + 64] : -1e30f;

        float m = fmaxf(fmaxf(a0, a1), a2);
        #pragma unroll
        for (int s = 16; s; s >>= 1) m = fmaxf(m, __shfl_xor_sync(0xFFFFFFFFu, m, s));
        float sum = __expf(a0 - m) + __expf(a1 - m) + ((lane < 17) ? __expf(a2 - m) : 0.f);
        #pragma unroll
        for (int s = 16; s; s >>= 1) sum += __shfl_xor_sync(0xFFFFFFFFu, sum, s);

        if (lane == 0) {
            float L = m + __logf(sum);                  // lse(conf row)
            int b = gw / PP;
            int p = gw - b * PP;
            int ti = d_bti[gw];
            const float* t = targets + (b * OO + ti) * 5;
            int cls = (int)t[4];

            float2 obv = ((const float2*)obj)[gw];
            float mo = fmaxf(obv.x, obv.y);
            float lseo = mo + __logf(__expf(obv.x - mo) + __expf(obv.y - mo));
            // CE of (C+1)-way combined logit at class cls+1: lse = L + lseo
            atomicAdd(&d_accB[b * 4 + 1], L + lseo - obv.y - crow[cls]);

            float4 pr = ((const float4*)priors)[p];
            float x1 = t[0], y1 = t[1], x2 = t[2], y2 = t[3];
            float lt0 = ((x1 + x2) * 0.5f - pr.x) / (0.1f * pr.z);
            float lt1 = ((y1 + y2) * 0.5f - pr.y) / (0.1f * pr.w);
            float lt2 = __logf((x2 - x1) / pr.z) * 5.0f;
            float lt3 = __logf((y2 - y1) / pr.w) * 5.0f;
            float4 ld = ((const float4*)loc)[gw];
            float sacc = 0.f, d;
            d = ld.x - lt0; sacc += (fabsf(d) < 1.f) ? 0.5f * d * d : fabsf(d) - 0.5f;
            d = ld.y - lt1; sacc += (fabsf(d) < 1.f) ? 0.5f * d * d : fabsf(d) - 0.5f;
            d = ld.z - lt2; sacc += (fabsf(d) < 1.f) ? 0.5f * d * d : fabsf(d) - 0.5f;
            d = ld.w - lt3; sacc += (fabsf(d) < 1.f) ? 0.5f * d * d : fabsf(d) - 0.5f;
            atomicAdd(&d_accB[b * 4 + 0], sacc);
        }
    }
}

// ---------------- top-k sum (exact radix select) — feeds BOTH losses ----------------
__global__ void __launch_bounds__(512) k_topk() {
    int b = blockIdx.x;
    const float* arr = d_ce + (size_t)b * PP;
    int k = 3 * d_npos[b];
    if (k > PP - 1) k = PP - 1;
    if (k <= 0) return;

    __shared__ unsigned hist[256];
    __shared__ unsigned s_prefix;
    __shared__ int s_krem;
    unsigned prefix = 0;
    int krem = k;

    for (int pass = 0; pass < 4; pass++) {
        if (threadIdx.x < 256) hist[threadIdx.x] = 0;
        __syncthreads();
        int shift = 24 - 8 * pass;
        for (int p = threadIdx.x; p < PP; p += 512) {
            unsigned u = __float_as_uint(arr[p]);
            if (pass == 0 || (u >> (shift + 8)) == prefix)
                atomicAdd(&hist[(u >> shift) & 0xFF], 1u);
        }
        __syncthreads();
        if (threadIdx.x == 0) {
            int cum = 0, bin = 255;
            for (; bin > 0; bin--) {
                int c = (int)hist[bin];
                if (cum + c >= krem) break;
                cum += c;
            }
            s_prefix = (prefix << 8) | (unsigned)bin;
            s_krem = krem - cum;
        }
        __syncthreads();
        prefix = s_prefix;
        krem = s_krem;
        __syncthreads();
    }
    unsigned vbits = prefix;
    float v = __uint_as_float(vbits);

    float sum = 0.f; int cnt = 0;
    for (int p = threadIdx.x; p < PP; p += 512) {
        float x = arr[p];
        if (__float_as_uint(x) > vbits) { sum += x; cnt++; }
    }
    __shared__ float ss[512];
    __shared__ int sc[512];
    ss[threadIdx.x] = sum; sc[threadIdx.x] = cnt;
    __syncthreads();
    for (int st = 256; st; st >>= 1) {
        if (threadIdx.x < st) {
            ss[threadIdx.x] += ss[threadIdx.x + st];
            sc[threadIdx.x] += sc[threadIdx.x + st];
        }
        __syncthreads();
    }
    if (threadIdx.x == 0) {
        float S = ss[0] + (float)(k - sc[0]) * v;   // exact top-k sum
        atomicAdd(&d_accB[b * 4 + 1], S);           // conf negatives
        atomicAdd(&d_accB[b * 4 + 2], S);           // obj negatives (same array)
    }
}

// ---------------- finalize (one warp) ----------------
__global__ void k_final(float* __restrict__ out) {
    int lane = threadIdx.x;
    float l0 = 0.f, l1 = 0.f, l2 = 0.f; int n = 0;
    for (int b = lane; b < BB; b += 32) {
        l0 += d_accB[b * 4 + 0];
        l1 += d_accB[b * 4 + 1];
        l2 += d_accB[b * 4 + 2];
        n  += d_npos[b];
    }
    #pragma unroll
    for (int s = 16; s; s >>= 1) {
        l0 += __shfl_xor_sync(0xFFFFFFFFu, l0, s);
        l1 += __shfl_xor_sync(0xFFFFFFFFu, l1, s);
        l2 += __shfl_xor_sync(0xFFFFFFFFu, l2, s);
        n  += __shfl_xor_sync(0xFFFFFFFFu, n,  s);
    }
    if (lane == 0) {
        float N = (float)n;
        out[0] = l0 / N;
        out[1] = l1 / N;
        out[2] = l2 / N;
    }
}

// ---------------- launch ----------------
extern "C" void kernel_launch(void* const* d_in, const int* in_sizes, int n_in,
                              void* d_out, int out_size) {
    const float* loc     = (const float*)d_in[0];
    const float* conf    = (const float*)d_in[1];
    const float* obj     = (const float*)d_in[2];
    const float* priors  = (const float*)d_in[3];
    const float* targets = (const float*)d_in[4];
    float* out = (float*)d_out;

    k_init<<<(BB * OO + 511) / 512, 512>>>();

    dim3 gm((PP + CHUNK - 1) / CHUNK, BB);     // 8 x 64 blocks
    k_match<<<gm, 256>>>(priors, targets);
    k_force<<<BB, 64>>>();

    k_neg<<<(BB * PP / 4) / 256, 256>>>(obj);
    k_pos<<<256, 256>>>(loc, conf, obj, priors, targets);

    k_topk<<<BB, 512>>>();
    k_final<<<1, 32>>>(out);
}